// round 11
// baseline (speedup 1.0000x reference)
#include <cuda_runtime.h>

#define DEV __device__ __forceinline__

constexpr int B    = 8;
constexpr int N    = 8192;
constexpr int M    = 2500;
constexpr int SPP  = 250;    // M / P(=10)

// joint tile: 32 queries x 512 candidates per block (CPT=4 for low reg pressure)
constexpr int QCH   = 79;              // query chunks (79*32 = 2528 >= 2500)
constexpr int QPB2  = 32;              // queries per block
constexpr int GCH   = 16;              // gt chunks per batch (16*512 = 8192)
constexpr int CPT   = 4;               // candidates per thread (2 packs)
constexpr int CPW   = 32 * CPT;        // 128 candidates per warp
constexpr int WCH   = N / CPW;         // 64 warp-level candidate chunks
constexpr int NBLK_C = B * QCH * GCH;  // 10112 chamfer blocks

constexpr int FB_F = 5 * B;                     // 40 fff blocks (512 thr each)
constexpr int FB_P = (B * M + 511) / 512;       // 40
constexpr int FB_G = (B * N / 4) / 512;         // 32 (float4 per thread)

constexpr float BIG = 3.2e38f;

// Partials — every slot written unconditionally; no init kernel, no atomics.
__device__ float g_rowPart[(size_t)WCH * B * M];  // d^2 row-min per warp-cand-chunk
__device__ float g_colPart[(size_t)QCH * B * N];  // d^2 col-min per query-chunk
__device__ float g_fffp[FB_F * 11];
__device__ float g_sum2[FB_P + FB_G];

// ---- packed fp32x2 helpers ----
DEV unsigned long long pack2(float lo, float hi) {
    unsigned long long r;
    asm("mov.b64 %0, {%1, %2};" : "=l"(r) : "f"(lo), "f"(hi));
    return r;
}
DEV void unpack2(unsigned long long v, float& lo, float& hi) {
    asm("mov.b64 {%0, %1}, %2;" : "=f"(lo), "=f"(hi) : "l"(v));
}
DEV unsigned long long fma2(unsigned long long a, unsigned long long b, unsigned long long c) {
    unsigned long long d;
    asm("fma.rn.f32x2 %0, %1, %2, %3;" : "=l"(d) : "l"(a), "l"(b), "l"(c));
    return d;
}
DEV unsigned long long add2(unsigned long long a, unsigned long long b) {
    unsigned long long d;
    asm("add.rn.f32x2 %0, %1, %2;" : "=l"(d) : "l"(a), "l"(b));
    return d;
}

DEV float blockReduceSum(float v) {
    __shared__ float sred[32];
    #pragma unroll
    for (int o = 16; o > 0; o >>= 1) v += __shfl_down_sync(0xffffffffu, v, o);
    int lane = threadIdx.x & 31, w = threadIdx.x >> 5;
    if (lane == 0) sred[w] = v;
    __syncthreads();
    int nw = (blockDim.x + 31) >> 5;
    v = (threadIdx.x < (unsigned)nw) ? sred[threadIdx.x] : 0.0f;
    if (w == 0) {
        #pragma unroll
        for (int o = 16; o > 0; o >>= 1) v += __shfl_down_sync(0xffffffffu, v, o);
    }
    __syncthreads();
    return v;
}

// ================= K1: pure chamfer, low-register variant =================
__global__ void __launch_bounds__(128, 12) k_mega(const float* __restrict__ pred,
                                                  const float* __restrict__ gt) {
    int bid = blockIdx.x;
    int tid = threadIdx.x;

    __shared__ ulonglong2 qs[QPB2][2];          // [0]={qx2,qy2} [1]={qz2,qn2}
    __shared__ float      rowTmp[4][QPB2 * 33]; // [warp][s*33 + lane]

    int gi = bid & (GCH - 1);
    int qi = (bid >> 4) % QCH;
    int b  = bid / (GCH * QCH);
    int w    = tid >> 5;
    int lane = tid & 31;
    int qbase = qi * QPB2;

    // stage queries pre-packed; pad with BIG norm
    if (tid < QPB2) {
        int m = qbase + tid;
        float x = 0.f, y = 0.f, z = 0.f, n = BIG;
        if (m < M) {
            const float* p = pred + (size_t)(b * M + m) * 3;
            x = p[0]; y = p[1]; z = p[2];
            n = x * x + y * y + z * z;
        }
        ulonglong2 u0, u1;
        u0.x = pack2(-2.f * x, -2.f * x);
        u0.y = pack2(-2.f * y, -2.f * y);
        u1.x = pack2(-2.f * z, -2.f * z);
        u1.y = pack2(n, n);
        qs[tid][0] = u0;
        qs[tid][1] = u1;
    }

    // this thread's 4 candidates -> registers (coalesced float4 x3)
    int cbase = gi * (4 * CPW) + w * CPW + lane * CPT;
    const float4* gsrc = (const float4*)(gt + (size_t)(b * N + cbase) * 3);
    float4 f0 = gsrc[0], f1 = gsrc[1], f2 = gsrc[2];
    unsigned long long cx[2], cy[2], cz[2], gn[2];
    {
        // candidates: (f0.x f0.y f0.z) (f0.w f1.x f1.y) (f1.z f1.w f2.x) (f2.y f2.z f2.w)
        cx[0] = pack2(f0.x, f0.w);
        cy[0] = pack2(f0.y, f1.x);
        cz[0] = pack2(f0.z, f1.y);
        gn[0] = pack2(f0.x*f0.x + f0.y*f0.y + f0.z*f0.z,
                      f0.w*f0.w + f1.x*f1.x + f1.y*f1.y);
        cx[1] = pack2(f1.z, f2.y);
        cy[1] = pack2(f1.w, f2.z);
        cz[1] = pack2(f2.x, f2.w);
        gn[1] = pack2(f1.z*f1.z + f1.w*f1.w + f2.x*f2.x,
                      f2.y*f2.y + f2.z*f2.z + f2.w*f2.w);
    }
    float cm[4];
    #pragma unroll
    for (int k = 0; k < 4; k++) cm[k] = BIG;
    __syncthreads();

    // main loop: per-thread work only; row value buffered via fire-and-forget STS
    #pragma unroll 4
    for (int s = 0; s < QPB2; s++) {
        ulonglong2 a = qs[s][0];
        ulonglong2 c = qs[s][1];

        unsigned long long t0 = fma2(cx[0], a.x, fma2(cy[0], a.y, fma2(cz[0], c.x, c.y)));
        unsigned long long t1 = fma2(cx[1], a.x, fma2(cy[1], a.y, fma2(cz[1], c.x, c.y)));

        float tl, th;
        unpack2(t0, tl, th); cm[0] = fminf(cm[0], tl); cm[1] = fminf(cm[1], th);
        unpack2(t1, tl, th); cm[2] = fminf(cm[2], tl); cm[3] = fminf(cm[3], th);

        float r0l, r0h, r1l, r1h;
        unpack2(add2(t0, gn[0]), r0l, r0h);
        unpack2(add2(t1, gn[1]), r1l, r1h);
        float rv = fminf(fminf(r0l, r0h), fminf(r1l, r1h));
        rowTmp[w][s * 33 + lane] = rv;     // conflict-free, no result latency
    }

    // col partials: add gn (unpacked), clamp, coalesced float4 write
    {
        float n0, n1, n2, n3;
        unpack2(gn[0], n0, n1);
        unpack2(gn[1], n2, n3);
        float4* outc = (float4*)(g_colPart + (size_t)qi * (B * N) + b * N + cbase);
        outc[0] = make_float4(fmaxf(cm[0] + n0, 0.f), fmaxf(cm[1] + n1, 0.f),
                              fmaxf(cm[2] + n2, 0.f), fmaxf(cm[3] + n3, 0.f));
    }
    __syncthreads();

    // row reduction: thread (ww, s) reduces 32 lanes of query s in warp ww's buffer.
    {
        int ww = tid >> 5;
        int s  = tid & 31;
        const float* src = &rowTmp[ww][s * 33];
        float f = src[0];
        #pragma unroll
        for (int l = 1; l < 32; l++) f = fminf(f, src[l]);
        int m = qbase + s;
        if (m < M) {
            int ch = gi * 4 + ww;          // warp-level candidate chunk [0,64)
            g_rowPart[(size_t)ch * (B * M) + b * M + m] = f;
        }
    }
}

// ================= K2: finish — fff partials + min over chunks =========
__global__ void __launch_bounds__(512) k_finish(const float* __restrict__ fff) {
    int bid = blockIdx.x;
    int tid = threadIdx.x;

    if (bid < FB_F) {
        int b = bid / 5;
        int m = (bid % 5) * 512 + tid;
        float v[11];
        #pragma unroll
        for (int i = 0; i < 11; i++) v[i] = 0.0f;
        if (m < M) {
            int idx = (b * M + m) * 3;
            float E = fff[idx], F = fff[idx + 1], G = fff[idx + 2];
            float A2  = fmaxf(E * G - F * F, 0.0f);
            float A   = sqrtf(A2);
            float inv = 1.0f / (A2 + 1e-20f);
            v[0] = E;        v[1] = G;        v[2] = inv;
            v[3] = E * inv;  v[4] = E * E * inv;
            v[5] = G * inv;  v[6] = G * G * inv;
            v[7] = F * F * inv;
            float d = E - G; v[8] = d * d * inv;
            if ((b & 1) == 0) {
                int idx2 = ((b + 1) * M + m) * 3;
                float E2 = fff[idx2], F2 = fff[idx2 + 1], G2 = fff[idx2 + 2];
                float dE = E - E2, dF = F - F2, dG = G - G2;
                v[9] = dE * dE + 2.0f * dF * dF + dG * dG;
            }
            v[10] = A;
        }
        #pragma unroll
        for (int k = 0; k < 11; k++) {
            float s = blockReduceSum(v[k]);
            if (tid == 0) g_fffp[bid * 11 + k] = s;
        }
        return;
    }

    int fb = bid - FB_F;
    float d = 0.0f;
    if (fb < FB_P) {
        int qi = fb * 512 + tid;           // [0, B*M)
        if (qi < B * M) {
            float f = g_rowPart[qi];
            #pragma unroll 8
            for (int ch = 1; ch < WCH; ch++)
                f = fminf(f, g_rowPart[(size_t)ch * (B * M) + qi]);
            d = fmaxf(f, 0.0f);
        }
    } else {
        int gi = (fb - FB_P) * 512 + tid;  // [0, B*N/4), exact
        const float4* cp = (const float4*)g_colPart;
        float4 f = cp[gi];
        for (int ch = 1; ch < QCH; ch++) {
            float4 v = cp[(size_t)ch * (B * N / 4) + gi];
            f.x = fminf(f.x, v.x); f.y = fminf(f.y, v.y);
            f.z = fminf(f.z, v.z); f.w = fminf(f.w, v.w);
        }
        d = f.x + f.y + f.z + f.w;          // already clamped at write
    }
    float s = blockReduceSum(d);
    if (tid == 0) g_sum2[fb] = s;
}

// ================= K3: final combine =================
__global__ void __launch_bounds__(512) k_final(const float* __restrict__ A_gt,
                                               float* __restrict__ out) {
    int tid = threadIdx.x;
    __shared__ float sA[FB_F];
    __shared__ float acc[12];

    #pragma unroll
    for (int k = 0; k < 10; k++) {
        float v = (tid < FB_F) ? g_fffp[tid * 11 + k] : 0.0f;
        float s = blockReduceSum(v);
        if (tid == 0) acc[k] = s;
    }
    {
        float v = (tid < FB_P) ? g_sum2[tid] : 0.0f;
        float s = blockReduceSum(v);
        if (tid == 0) acc[10] = s;
        v = (tid < FB_G) ? g_sum2[FB_P + tid] : 0.0f;
        s = blockReduceSum(v);
        if (tid == 0) acc[11] = s;
    }
    if (tid < FB_F) sA[tid] = g_fffp[tid * 11 + 10];
    __syncthreads();

    if (tid == 0) {
        float BM = (float)(B * M);
        float L_chd = acc[10] / BM + acc[11] / (float)(B * N);
        float sE = acc[0], sG = acc[1], sInv = acc[2];
        float sEinv = acc[3], sE2inv = acc[4], sGinv = acc[5], sG2inv = acc[6];
        float sF2inv = acc[7], sStretch = acc[8], sMc = acc[9];
        float mE = sE / BM, mG = sG / BM;
        float L_E  = (sE2inv - 2.0f * mE * sEinv + mE * mE * sInv) / BM;
        float L_G  = (sG2inv - 2.0f * mG * sGinv + mG * mG * sInv) / BM;
        float L_F  = sF2inv  / BM;
        float L_st = sStretch / BM;
        float L_mc = sMc / (0.5f * BM);
        float L_ol = 0.0f;
        for (int b = 0; b < B; b++) {
            float at = 0.0f;
            for (int j = 0; j < 5; j++) at += sA[b * 5 + j];
            at *= (1.0f / (float)SPP);
            float r = fmaxf(at - A_gt[b], 0.0f);
            L_ol += r * r;
        }
        L_ol *= (1.0f / (float)B);
        out[0] = L_chd + L_mc + L_F + L_E + L_G + L_st + L_ol;
    }
}

extern "C" void kernel_launch(void* const* d_in, const int* in_sizes, int n_in,
                              void* d_out, int out_size) {
    (void)in_sizes; (void)n_in; (void)out_size;
    const float* pc_gt   = (const float*)d_in[0];
    const float* pc_pred = (const float*)d_in[1];
    const float* fffp    = (const float*)d_in[2];
    const float* A_gt    = (const float*)d_in[3];
    float* out = (float*)d_out;

    k_mega  <<<NBLK_C, 128>>>(pc_pred, pc_gt);
    k_finish<<<FB_F + FB_P + FB_G, 512>>>(fffp);
    k_final <<<1, 512>>>(A_gt, out);
}

// round 13
// speedup vs baseline: 1.0960x; 1.0960x over previous
#include <cuda_runtime.h>

#define DEV __device__ __forceinline__

constexpr int B    = 8;
constexpr int N    = 8192;
constexpr int M    = 2500;
constexpr int SPP  = 250;    // M / P(=10)

// joint tile: 32 queries x 1024 candidates per block (CPT=8), ILP=2 queries/iter
constexpr int QCH   = 79;              // query chunks (79*32 = 2528 >= 2500)
constexpr int QPB2  = 32;              // queries per block
constexpr int GCH   = 8;               // gt chunks per batch (8*1024 = 8192)
constexpr int CPT   = 8;               // candidates per thread (4 packs)
constexpr int CPW   = 32 * CPT;        // 256 candidates per warp
constexpr int WCH   = N / CPW;         // 32 warp-level candidate chunks
constexpr int NBLK_C = B * QCH * GCH;  // 5056 chamfer blocks

constexpr int FB_F = 5 * B;                     // 40 fff blocks (512 thr each)
constexpr int FB_P = (B * M + 511) / 512;       // 40
constexpr int FB_G = (B * N / 4) / 512;         // 32 (float4 per thread)
constexpr int FB_T = FB_F + FB_P + FB_G;        // 112 finish blocks

constexpr float BIG = 3.2e38f;

// Partials — every slot written unconditionally; no init kernel, no atomics on data.
__device__ float    g_rowPart[(size_t)WCH * B * M];
__device__ float    g_colPart[(size_t)QCH * B * N];
__device__ float    g_fffp[FB_F * 11];
__device__ float    g_sum2[FB_P + FB_G];
__device__ unsigned g_done;              // zero-init; reset by last block each launch

// ---- packed fp32x2 helpers ----
typedef unsigned long long ull;
DEV ull pack2(float lo, float hi) {
    ull r; asm("mov.b64 %0, {%1, %2};" : "=l"(r) : "f"(lo), "f"(hi)); return r;
}
DEV void unpack2(ull v, float& lo, float& hi) {
    asm("mov.b64 {%0, %1}, %2;" : "=f"(lo), "=f"(hi) : "l"(v));
}
DEV ull fma2(ull a, ull b, ull c) {
    ull d; asm("fma.rn.f32x2 %0, %1, %2, %3;" : "=l"(d) : "l"(a), "l"(b), "l"(c)); return d;
}
DEV ull add2(ull a, ull b) {
    ull d; asm("add.rn.f32x2 %0, %1, %2;" : "=l"(d) : "l"(a), "l"(b)); return d;
}

DEV float blockReduceSum(float v) {
    __shared__ float sred[32];
    #pragma unroll
    for (int o = 16; o > 0; o >>= 1) v += __shfl_down_sync(0xffffffffu, v, o);
    int lane = threadIdx.x & 31, w = threadIdx.x >> 5;
    if (lane == 0) sred[w] = v;
    __syncthreads();
    int nw = (blockDim.x + 31) >> 5;
    v = (threadIdx.x < (unsigned)nw) ? sred[threadIdx.x] : 0.0f;
    if (w == 0) {
        #pragma unroll
        for (int o = 16; o > 0; o >>= 1) v += __shfl_down_sync(0xffffffffu, v, o);
    }
    __syncthreads();
    return v;
}

// ================= K1: pure chamfer, 2 independent query chains per iter ==========
__global__ void __launch_bounds__(128, 6) k_mega(const float* __restrict__ pred,
                                                 const float* __restrict__ gt) {
    int bid = blockIdx.x;
    int tid = threadIdx.x;

    __shared__ ulonglong2 qs[QPB2][2];          // [0]={qx2,qy2} [1]={qz2,qn2}
    __shared__ float      rowTmp[4][QPB2 * 33]; // [warp][s*33 + lane]

    int gi = bid & (GCH - 1);
    int qi = (bid >> 3) % QCH;
    int b  = bid / (GCH * QCH);
    int w    = tid >> 5;
    int lane = tid & 31;
    int qbase = qi * QPB2;

    // stage queries pre-packed; pad with BIG norm
    if (tid < QPB2) {
        int m = qbase + tid;
        float x = 0.f, y = 0.f, z = 0.f, n = BIG;
        if (m < M) {
            const float* p = pred + (size_t)(b * M + m) * 3;
            x = p[0]; y = p[1]; z = p[2];
            n = x * x + y * y + z * z;
        }
        ulonglong2 u0, u1;
        u0.x = pack2(-2.f * x, -2.f * x);
        u0.y = pack2(-2.f * y, -2.f * y);
        u1.x = pack2(-2.f * z, -2.f * z);
        u1.y = pack2(n, n);
        qs[tid][0] = u0;
        qs[tid][1] = u1;
    }

    // this thread's 8 candidates -> registers (coalesced float4 x6)
    int cbase = gi * (4 * CPW) + w * CPW + lane * CPT;
    const float4* gsrc = (const float4*)(gt + (size_t)(b * N + cbase) * 3);
    float4 f0 = gsrc[0], f1 = gsrc[1], f2 = gsrc[2];
    float4 f3 = gsrc[3], f4 = gsrc[4], f5 = gsrc[5];
    float cf[24] = {f0.x,f0.y,f0.z,f0.w, f1.x,f1.y,f1.z,f1.w,
                    f2.x,f2.y,f2.z,f2.w, f3.x,f3.y,f3.z,f3.w,
                    f4.x,f4.y,f4.z,f4.w, f5.x,f5.y,f5.z,f5.w};
    ull cx[4], cy[4], cz[4], gn[4];
    #pragma unroll
    for (int k = 0; k < 4; k++) {
        float x0 = cf[6*k+0], y0 = cf[6*k+1], z0 = cf[6*k+2];
        float x1 = cf[6*k+3], y1 = cf[6*k+4], z1 = cf[6*k+5];
        cx[k] = pack2(x0, x1);
        cy[k] = pack2(y0, y1);
        cz[k] = pack2(z0, z1);
        gn[k] = pack2(x0*x0 + y0*y0 + z0*z0, x1*x1 + y1*y1 + z1*z1);
    }
    float cm[8];
    #pragma unroll
    for (int k = 0; k < 8; k++) cm[k] = BIG;
    __syncthreads();

    // main loop: two independent query chains (s, s+16) per iteration
    #pragma unroll 2
    for (int s = 0; s < QPB2 / 2; s++) {
        ulonglong2 aA = qs[s][0],      cA = qs[s][1];
        ulonglong2 aB = qs[s + 16][0], cB = qs[s + 16][1];

        ull tA0 = fma2(cx[0], aA.x, fma2(cy[0], aA.y, fma2(cz[0], cA.x, cA.y)));
        ull tB0 = fma2(cx[0], aB.x, fma2(cy[0], aB.y, fma2(cz[0], cB.x, cB.y)));
        ull tA1 = fma2(cx[1], aA.x, fma2(cy[1], aA.y, fma2(cz[1], cA.x, cA.y)));
        ull tB1 = fma2(cx[1], aB.x, fma2(cy[1], aB.y, fma2(cz[1], cB.x, cB.y)));
        ull tA2 = fma2(cx[2], aA.x, fma2(cy[2], aA.y, fma2(cz[2], cA.x, cA.y)));
        ull tB2 = fma2(cx[2], aB.x, fma2(cy[2], aB.y, fma2(cz[2], cB.x, cB.y)));
        ull tA3 = fma2(cx[3], aA.x, fma2(cy[3], aA.y, fma2(cz[3], cA.x, cA.y)));
        ull tB3 = fma2(cx[3], aB.x, fma2(cy[3], aB.y, fma2(cz[3], cB.x, cB.y)));

        float l, h;
        // col-min updates (pre-gn), both chains
        unpack2(tA0, l, h); cm[0] = fminf(cm[0], l); cm[1] = fminf(cm[1], h);
        unpack2(tB0, l, h); cm[0] = fminf(cm[0], l); cm[1] = fminf(cm[1], h);
        unpack2(tA1, l, h); cm[2] = fminf(cm[2], l); cm[3] = fminf(cm[3], h);
        unpack2(tB1, l, h); cm[2] = fminf(cm[2], l); cm[3] = fminf(cm[3], h);
        unpack2(tA2, l, h); cm[4] = fminf(cm[4], l); cm[5] = fminf(cm[5], h);
        unpack2(tB2, l, h); cm[4] = fminf(cm[4], l); cm[5] = fminf(cm[5], h);
        unpack2(tA3, l, h); cm[6] = fminf(cm[6], l); cm[7] = fminf(cm[7], h);
        unpack2(tB3, l, h); cm[6] = fminf(cm[6], l); cm[7] = fminf(cm[7], h);

        // row-min chain A
        {
            float r0l, r0h, r1l, r1h, r2l, r2h, r3l, r3h;
            unpack2(add2(tA0, gn[0]), r0l, r0h);
            unpack2(add2(tA1, gn[1]), r1l, r1h);
            unpack2(add2(tA2, gn[2]), r2l, r2h);
            unpack2(add2(tA3, gn[3]), r3l, r3h);
            float rv = fminf(fminf(fminf(r0l, r0h), fminf(r1l, r1h)),
                             fminf(fminf(r2l, r2h), fminf(r3l, r3h)));
            rowTmp[w][s * 33 + lane] = rv;
        }
        // row-min chain B
        {
            float r0l, r0h, r1l, r1h, r2l, r2h, r3l, r3h;
            unpack2(add2(tB0, gn[0]), r0l, r0h);
            unpack2(add2(tB1, gn[1]), r1l, r1h);
            unpack2(add2(tB2, gn[2]), r2l, r2h);
            unpack2(add2(tB3, gn[3]), r3l, r3h);
            float rv = fminf(fminf(fminf(r0l, r0h), fminf(r1l, r1h)),
                             fminf(fminf(r2l, r2h), fminf(r3l, r3h)));
            rowTmp[w][(s + 16) * 33 + lane] = rv;
        }
    }

    // col partials: add gn (unpacked), clamp, coalesced float4 writes
    {
        float n0, n1, n2, n3, n4, n5, n6, n7;
        unpack2(gn[0], n0, n1); unpack2(gn[1], n2, n3);
        unpack2(gn[2], n4, n5); unpack2(gn[3], n6, n7);
        float4* outc = (float4*)(g_colPart + (size_t)qi * (B * N) + b * N + cbase);
        outc[0] = make_float4(fmaxf(cm[0] + n0, 0.f), fmaxf(cm[1] + n1, 0.f),
                              fmaxf(cm[2] + n2, 0.f), fmaxf(cm[3] + n3, 0.f));
        outc[1] = make_float4(fmaxf(cm[4] + n4, 0.f), fmaxf(cm[5] + n5, 0.f),
                              fmaxf(cm[6] + n6, 0.f), fmaxf(cm[7] + n7, 0.f));
    }
    __syncthreads();

    // row reduction: thread (ww, s) reduces 32 lanes of query s in warp ww's buffer
    {
        int ww = tid >> 5;
        int s  = tid & 31;
        const float* src = &rowTmp[ww][s * 33];
        float f = src[0];
        #pragma unroll
        for (int l2 = 1; l2 < 32; l2++) f = fminf(f, src[l2]);
        int m = qbase + s;
        if (m < M) {
            int ch = gi * 4 + ww;
            g_rowPart[(size_t)ch * (B * M) + b * M + m] = f;
        }
    }
}

// ====== K2: finish — fff partials + chunk mins; LAST block does final combine =====
__global__ void __launch_bounds__(512) k_finish(const float* __restrict__ fff,
                                                const float* __restrict__ A_gt,
                                                float* __restrict__ out) {
    int bid = blockIdx.x;
    int tid = threadIdx.x;
    __shared__ unsigned sLast;

    if (bid < FB_F) {
        int b = bid / 5;
        int m = (bid % 5) * 512 + tid;
        float v[11];
        #pragma unroll
        for (int i = 0; i < 11; i++) v[i] = 0.0f;
        if (m < M) {
            int idx = (b * M + m) * 3;
            float E = fff[idx], F = fff[idx + 1], G = fff[idx + 2];
            float A2  = fmaxf(E * G - F * F, 0.0f);
            float A   = sqrtf(A2);
            float inv = 1.0f / (A2 + 1e-20f);
            v[0] = E;        v[1] = G;        v[2] = inv;
            v[3] = E * inv;  v[4] = E * E * inv;
            v[5] = G * inv;  v[6] = G * G * inv;
            v[7] = F * F * inv;
            float d = E - G; v[8] = d * d * inv;
            if ((b & 1) == 0) {
                int idx2 = ((b + 1) * M + m) * 3;
                float E2 = fff[idx2], F2 = fff[idx2 + 1], G2 = fff[idx2 + 2];
                float dE = E - E2, dF = F - F2, dG = G - G2;
                v[9] = dE * dE + 2.0f * dF * dF + dG * dG;
            }
            v[10] = A;
        }
        #pragma unroll
        for (int k = 0; k < 11; k++) {
            float s = blockReduceSum(v[k]);
            if (tid == 0) g_fffp[bid * 11 + k] = s;
        }
    } else {
        int fb = bid - FB_F;
        float d = 0.0f;
        if (fb < FB_P) {
            int qi = fb * 512 + tid;
            if (qi < B * M) {
                float f = g_rowPart[qi];
                #pragma unroll 8
                for (int ch = 1; ch < WCH; ch++)
                    f = fminf(f, g_rowPart[(size_t)ch * (B * M) + qi]);
                d = fmaxf(f, 0.0f);
            }
        } else {
            int gi = (fb - FB_P) * 512 + tid;
            const float4* cp = (const float4*)g_colPart;
            float4 f = cp[gi];
            for (int ch = 1; ch < QCH; ch++) {
                float4 v = cp[(size_t)ch * (B * N / 4) + gi];
                f.x = fminf(f.x, v.x); f.y = fminf(f.y, v.y);
                f.z = fminf(f.z, v.z); f.w = fminf(f.w, v.w);
            }
            d = f.x + f.y + f.z + f.w;
        }
        float s = blockReduceSum(d);
        if (tid == 0) g_sum2[fb] = s;
    }

    // last-block-does-final
    __threadfence();
    if (tid == 0) sLast = (atomicAdd(&g_done, 1u) == (unsigned)(FB_T - 1));
    __syncthreads();
    if (!sLast) return;
    __threadfence();   // acquire: see all partials

    __shared__ float sA[FB_F];
    __shared__ float acc[12];
    #pragma unroll
    for (int k = 0; k < 10; k++) {
        float v = (tid < FB_F) ? g_fffp[tid * 11 + k] : 0.0f;
        float s = blockReduceSum(v);
        if (tid == 0) acc[k] = s;
    }
    {
        float v = (tid < FB_P) ? g_sum2[tid] : 0.0f;
        float s = blockReduceSum(v);
        if (tid == 0) acc[10] = s;
        v = (tid < FB_G) ? g_sum2[FB_P + tid] : 0.0f;
        s = blockReduceSum(v);
        if (tid == 0) acc[11] = s;
    }
    if (tid < FB_F) sA[tid] = g_fffp[tid * 11 + 10];
    __syncthreads();

    if (tid == 0) {
        float BM = (float)(B * M);
        float L_chd = acc[10] / BM + acc[11] / (float)(B * N);
        float sE = acc[0], sG = acc[1], sInv = acc[2];
        float sEinv = acc[3], sE2inv = acc[4], sGinv = acc[5], sG2inv = acc[6];
        float sF2inv = acc[7], sStretch = acc[8], sMc = acc[9];
        float mE = sE / BM, mG = sG / BM;
        float L_E  = (sE2inv - 2.0f * mE * sEinv + mE * mE * sInv) / BM;
        float L_G  = (sG2inv - 2.0f * mG * sGinv + mG * mG * sInv) / BM;
        float L_F  = sF2inv  / BM;
        float L_st = sStretch / BM;
        float L_mc = sMc / (0.5f * BM);
        float L_ol = 0.0f;
        for (int b = 0; b < B; b++) {
            float at = 0.0f;
            for (int j = 0; j < 5; j++) at += sA[b * 5 + j];
            at *= (1.0f / (float)SPP);
            float r = fmaxf(at - A_gt[b], 0.0f);
            L_ol += r * r;
        }
        L_ol *= (1.0f / (float)B);
        out[0] = L_chd + L_mc + L_F + L_E + L_G + L_st + L_ol;
        g_done = 0;   // reset for next launch/replay
    }
}

extern "C" void kernel_launch(void* const* d_in, const int* in_sizes, int n_in,
                              void* d_out, int out_size) {
    (void)in_sizes; (void)n_in; (void)out_size;
    const float* pc_gt   = (const float*)d_in[0];
    const float* pc_pred = (const float*)d_in[1];
    const float* fffp    = (const float*)d_in[2];
    const float* A_gt    = (const float*)d_in[3];
    float* out = (float*)d_out;

    k_mega  <<<NBLK_C, 128>>>(pc_pred, pc_gt);
    k_finish<<<FB_T, 512>>>(fffp, A_gt, out);
}

// round 14
// speedup vs baseline: 1.1330x; 1.0337x over previous
#include <cuda_runtime.h>

#define DEV __device__ __forceinline__

constexpr int B    = 8;
constexpr int N    = 8192;
constexpr int M    = 2500;
constexpr int SPP  = 250;    // M / P(=10)

// joint tile: 64 queries x 1024 candidates per block (CPT=8), ILP=2 queries/iter
constexpr int QCH   = 40;              // query chunks (40*64 = 2560 >= 2500)
constexpr int QPB2  = 64;              // queries per block
constexpr int GCH   = 8;               // gt chunks per batch (8*1024 = 8192)
constexpr int CPT   = 8;               // candidates per thread (4 packs)
constexpr int CPW   = 32 * CPT;        // 256 candidates per warp
constexpr int WCH   = N / CPW;         // 32 warp-level candidate chunks
constexpr int NBLK_C = B * QCH * GCH;  // 2560 chamfer blocks

// k_finish: 128-thread blocks for parallelism
constexpr int FT   = 128;
constexpr int FB_F = 20 * B;                    // 160 fff blocks (128 thr)
constexpr int FB_P = (B * M + FT - 1) / FT;     // 157
constexpr int FB_G = (B * N / 4) / FT;          // 128 (float4 per thread)
constexpr int FB_T = FB_F + FB_P + FB_G;        // 445

constexpr float BIG = 3.2e38f;

// Partials — every slot written unconditionally; no init kernel, no atomics on data.
__device__ float    g_rowPart[(size_t)WCH * B * M];
__device__ float    g_colPart[(size_t)QCH * B * N];   // 10.5 MB
__device__ float    g_fffp[FB_F * 11];
__device__ float    g_sum2[FB_P + FB_G];
__device__ unsigned g_done;              // zero-init; reset by last block each launch

// ---- packed fp32x2 helpers ----
typedef unsigned long long ull;
DEV ull pack2(float lo, float hi) {
    ull r; asm("mov.b64 %0, {%1, %2};" : "=l"(r) : "f"(lo), "f"(hi)); return r;
}
DEV void unpack2(ull v, float& lo, float& hi) {
    asm("mov.b64 {%0, %1}, %2;" : "=f"(lo), "=f"(hi) : "l"(v));
}
DEV ull fma2(ull a, ull b, ull c) {
    ull d; asm("fma.rn.f32x2 %0, %1, %2, %3;" : "=l"(d) : "l"(a), "l"(b), "l"(c)); return d;
}
DEV ull add2(ull a, ull b) {
    ull d; asm("add.rn.f32x2 %0, %1, %2;" : "=l"(d) : "l"(a), "l"(b)); return d;
}

DEV float blockReduceSum(float v) {
    __shared__ float sred[32];
    #pragma unroll
    for (int o = 16; o > 0; o >>= 1) v += __shfl_down_sync(0xffffffffu, v, o);
    int lane = threadIdx.x & 31, w = threadIdx.x >> 5;
    if (lane == 0) sred[w] = v;
    __syncthreads();
    int nw = (blockDim.x + 31) >> 5;
    v = (threadIdx.x < (unsigned)nw) ? sred[threadIdx.x] : 0.0f;
    if (w == 0) {
        #pragma unroll
        for (int o = 16; o > 0; o >>= 1) v += __shfl_down_sync(0xffffffffu, v, o);
    }
    __syncthreads();
    return v;
}

// ================= K1: pure chamfer, 2 independent query chains per iter ==========
__global__ void __launch_bounds__(128, 6) k_mega(const float* __restrict__ pred,
                                                 const float* __restrict__ gt) {
    int bid = blockIdx.x;
    int tid = threadIdx.x;

    __shared__ ulonglong2 qs[QPB2][2];          // [0]={qx2,qy2} [1]={qz2,qn2}
    __shared__ float      rowTmp[4][QPB2 * 33]; // [warp][s*33 + lane]  (33.8 KB)

    int gi = bid & (GCH - 1);
    int qi = (bid >> 3) % QCH;
    int b  = bid / (GCH * QCH);
    int w    = tid >> 5;
    int lane = tid & 31;
    int qbase = qi * QPB2;

    // stage queries pre-packed; pad with BIG norm
    if (tid < QPB2) {
        int m = qbase + tid;
        float x = 0.f, y = 0.f, z = 0.f, n = BIG;
        if (m < M) {
            const float* p = pred + (size_t)(b * M + m) * 3;
            x = p[0]; y = p[1]; z = p[2];
            n = x * x + y * y + z * z;
        }
        ulonglong2 u0, u1;
        u0.x = pack2(-2.f * x, -2.f * x);
        u0.y = pack2(-2.f * y, -2.f * y);
        u1.x = pack2(-2.f * z, -2.f * z);
        u1.y = pack2(n, n);
        qs[tid][0] = u0;
        qs[tid][1] = u1;
    }

    // this thread's 8 candidates -> registers (coalesced float4 x6)
    int cbase = gi * (4 * CPW) + w * CPW + lane * CPT;
    const float4* gsrc = (const float4*)(gt + (size_t)(b * N + cbase) * 3);
    float4 f0 = gsrc[0], f1 = gsrc[1], f2 = gsrc[2];
    float4 f3 = gsrc[3], f4 = gsrc[4], f5 = gsrc[5];
    float cf[24] = {f0.x,f0.y,f0.z,f0.w, f1.x,f1.y,f1.z,f1.w,
                    f2.x,f2.y,f2.z,f2.w, f3.x,f3.y,f3.z,f3.w,
                    f4.x,f4.y,f4.z,f4.w, f5.x,f5.y,f5.z,f5.w};
    ull cx[4], cy[4], cz[4], gn[4];
    #pragma unroll
    for (int k = 0; k < 4; k++) {
        float x0 = cf[6*k+0], y0 = cf[6*k+1], z0 = cf[6*k+2];
        float x1 = cf[6*k+3], y1 = cf[6*k+4], z1 = cf[6*k+5];
        cx[k] = pack2(x0, x1);
        cy[k] = pack2(y0, y1);
        cz[k] = pack2(z0, z1);
        gn[k] = pack2(x0*x0 + y0*y0 + z0*z0, x1*x1 + y1*y1 + z1*z1);
    }
    float cm[8];
    #pragma unroll
    for (int k = 0; k < 8; k++) cm[k] = BIG;
    __syncthreads();

    // main loop: two independent query chains (s, s+32) per iteration
    #pragma unroll 2
    for (int s = 0; s < QPB2 / 2; s++) {
        ulonglong2 aA = qs[s][0],      cA = qs[s][1];
        ulonglong2 aB = qs[s + 32][0], cB = qs[s + 32][1];

        ull tA0 = fma2(cx[0], aA.x, fma2(cy[0], aA.y, fma2(cz[0], cA.x, cA.y)));
        ull tB0 = fma2(cx[0], aB.x, fma2(cy[0], aB.y, fma2(cz[0], cB.x, cB.y)));
        ull tA1 = fma2(cx[1], aA.x, fma2(cy[1], aA.y, fma2(cz[1], cA.x, cA.y)));
        ull tB1 = fma2(cx[1], aB.x, fma2(cy[1], aB.y, fma2(cz[1], cB.x, cB.y)));
        ull tA2 = fma2(cx[2], aA.x, fma2(cy[2], aA.y, fma2(cz[2], cA.x, cA.y)));
        ull tB2 = fma2(cx[2], aB.x, fma2(cy[2], aB.y, fma2(cz[2], cB.x, cB.y)));
        ull tA3 = fma2(cx[3], aA.x, fma2(cy[3], aA.y, fma2(cz[3], cA.x, cA.y)));
        ull tB3 = fma2(cx[3], aB.x, fma2(cy[3], aB.y, fma2(cz[3], cB.x, cB.y)));

        float l, h;
        unpack2(tA0, l, h); cm[0] = fminf(cm[0], l); cm[1] = fminf(cm[1], h);
        unpack2(tB0, l, h); cm[0] = fminf(cm[0], l); cm[1] = fminf(cm[1], h);
        unpack2(tA1, l, h); cm[2] = fminf(cm[2], l); cm[3] = fminf(cm[3], h);
        unpack2(tB1, l, h); cm[2] = fminf(cm[2], l); cm[3] = fminf(cm[3], h);
        unpack2(tA2, l, h); cm[4] = fminf(cm[4], l); cm[5] = fminf(cm[5], h);
        unpack2(tB2, l, h); cm[4] = fminf(cm[4], l); cm[5] = fminf(cm[5], h);
        unpack2(tA3, l, h); cm[6] = fminf(cm[6], l); cm[7] = fminf(cm[7], h);
        unpack2(tB3, l, h); cm[6] = fminf(cm[6], l); cm[7] = fminf(cm[7], h);

        {
            float r0l, r0h, r1l, r1h, r2l, r2h, r3l, r3h;
            unpack2(add2(tA0, gn[0]), r0l, r0h);
            unpack2(add2(tA1, gn[1]), r1l, r1h);
            unpack2(add2(tA2, gn[2]), r2l, r2h);
            unpack2(add2(tA3, gn[3]), r3l, r3h);
            float rv = fminf(fminf(fminf(r0l, r0h), fminf(r1l, r1h)),
                             fminf(fminf(r2l, r2h), fminf(r3l, r3h)));
            rowTmp[w][s * 33 + lane] = rv;
        }
        {
            float r0l, r0h, r1l, r1h, r2l, r2h, r3l, r3h;
            unpack2(add2(tB0, gn[0]), r0l, r0h);
            unpack2(add2(tB1, gn[1]), r1l, r1h);
            unpack2(add2(tB2, gn[2]), r2l, r2h);
            unpack2(add2(tB3, gn[3]), r3l, r3h);
            float rv = fminf(fminf(fminf(r0l, r0h), fminf(r1l, r1h)),
                             fminf(fminf(r2l, r2h), fminf(r3l, r3h)));
            rowTmp[w][(s + 32) * 33 + lane] = rv;
        }
    }

    // col partials: add gn (unpacked), clamp, coalesced float4 writes
    {
        float n0, n1, n2, n3, n4, n5, n6, n7;
        unpack2(gn[0], n0, n1); unpack2(gn[1], n2, n3);
        unpack2(gn[2], n4, n5); unpack2(gn[3], n6, n7);
        float4* outc = (float4*)(g_colPart + (size_t)qi * (B * N) + b * N + cbase);
        outc[0] = make_float4(fmaxf(cm[0] + n0, 0.f), fmaxf(cm[1] + n1, 0.f),
                              fmaxf(cm[2] + n2, 0.f), fmaxf(cm[3] + n3, 0.f));
        outc[1] = make_float4(fmaxf(cm[4] + n4, 0.f), fmaxf(cm[5] + n5, 0.f),
                              fmaxf(cm[6] + n6, 0.f), fmaxf(cm[7] + n7, 0.f));
    }
    __syncthreads();

    // row reduction: 4 warps x 64 queries -> 256 entries, 2 per thread
    for (int idx = tid; idx < 4 * QPB2; idx += 128) {
        int ww = idx >> 6;             // /QPB2
        int s  = idx & (QPB2 - 1);
        const float* src = &rowTmp[ww][s * 33];
        float f = src[0];
        #pragma unroll
        for (int l2 = 1; l2 < 32; l2++) f = fminf(f, src[l2]);
        int m = qbase + s;
        if (m < M) {
            int ch = gi * 4 + ww;
            g_rowPart[(size_t)ch * (B * M) + b * M + m] = f;
        }
    }
}

// ====== K2: finish (128-thr blocks) — partials; LAST block does final combine =====
__global__ void __launch_bounds__(FT) k_finish(const float* __restrict__ fff,
                                               const float* __restrict__ A_gt,
                                               float* __restrict__ out) {
    int bid = blockIdx.x;
    int tid = threadIdx.x;
    __shared__ unsigned sLast;

    if (bid < FB_F) {
        int b = bid / 20;
        int m = (bid % 20) * FT + tid;
        float v[11];
        #pragma unroll
        for (int i = 0; i < 11; i++) v[i] = 0.0f;
        if (m < M) {
            int idx = (b * M + m) * 3;
            float E = fff[idx], F = fff[idx + 1], G = fff[idx + 2];
            float A2  = fmaxf(E * G - F * F, 0.0f);
            float A   = sqrtf(A2);
            float inv = 1.0f / (A2 + 1e-20f);
            v[0] = E;        v[1] = G;        v[2] = inv;
            v[3] = E * inv;  v[4] = E * E * inv;
            v[5] = G * inv;  v[6] = G * G * inv;
            v[7] = F * F * inv;
            float d = E - G; v[8] = d * d * inv;
            if ((b & 1) == 0) {
                int idx2 = ((b + 1) * M + m) * 3;
                float E2 = fff[idx2], F2 = fff[idx2 + 1], G2 = fff[idx2 + 2];
                float dE = E - E2, dF = F - F2, dG = G - G2;
                v[9] = dE * dE + 2.0f * dF * dF + dG * dG;
            }
            v[10] = A;
        }
        #pragma unroll
        for (int k = 0; k < 11; k++) {
            float s = blockReduceSum(v[k]);
            if (tid == 0) g_fffp[bid * 11 + k] = s;
        }
    } else {
        int fb = bid - FB_F;
        float d = 0.0f;
        if (fb < FB_P) {
            int qi = fb * FT + tid;
            if (qi < B * M) {
                float f = g_rowPart[qi];
                #pragma unroll 8
                for (int ch = 1; ch < WCH; ch++)
                    f = fminf(f, g_rowPart[(size_t)ch * (B * M) + qi]);
                d = fmaxf(f, 0.0f);
            }
        } else {
            int gi = (fb - FB_P) * FT + tid;   // [0, B*N/4), exact
            const float4* cp = (const float4*)g_colPart;
            float4 f = cp[gi];
            #pragma unroll 8
            for (int ch = 1; ch < QCH; ch++) {
                float4 v = cp[(size_t)ch * (B * N / 4) + gi];
                f.x = fminf(f.x, v.x); f.y = fminf(f.y, v.y);
                f.z = fminf(f.z, v.z); f.w = fminf(f.w, v.w);
            }
            d = f.x + f.y + f.z + f.w;          // already clamped at write
        }
        float s = blockReduceSum(d);
        if (tid == 0) g_sum2[fb] = s;
    }

    // last-block-does-final
    __threadfence();
    if (tid == 0) sLast = (atomicAdd(&g_done, 1u) == (unsigned)(FB_T - 1));
    __syncthreads();
    if (!sLast) return;
    __threadfence();   // acquire

    __shared__ float sA[FB_F];
    __shared__ float acc[12];
    #pragma unroll
    for (int k = 0; k < 10; k++) {
        float v = 0.0f;
        for (int j = tid; j < FB_F; j += FT) v += g_fffp[j * 11 + k];
        float s = blockReduceSum(v);
        if (tid == 0) acc[k] = s;
    }
    {
        float v = 0.0f;
        for (int j = tid; j < FB_P; j += FT) v += g_sum2[j];
        float s = blockReduceSum(v);
        if (tid == 0) acc[10] = s;
        v = 0.0f;
        for (int j = tid; j < FB_G; j += FT) v += g_sum2[FB_P + j];
        s = blockReduceSum(v);
        if (tid == 0) acc[11] = s;
    }
    for (int j = tid; j < FB_F; j += FT) sA[j] = g_fffp[j * 11 + 10];
    __syncthreads();

    if (tid == 0) {
        float BM = (float)(B * M);
        float L_chd = acc[10] / BM + acc[11] / (float)(B * N);
        float sE = acc[0], sG = acc[1], sInv = acc[2];
        float sEinv = acc[3], sE2inv = acc[4], sGinv = acc[5], sG2inv = acc[6];
        float sF2inv = acc[7], sStretch = acc[8], sMc = acc[9];
        float mE = sE / BM, mG = sG / BM;
        float L_E  = (sE2inv - 2.0f * mE * sEinv + mE * mE * sInv) / BM;
        float L_G  = (sG2inv - 2.0f * mG * sGinv + mG * mG * sInv) / BM;
        float L_F  = sF2inv  / BM;
        float L_st = sStretch / BM;
        float L_mc = sMc / (0.5f * BM);
        float L_ol = 0.0f;
        for (int b = 0; b < B; b++) {
            float at = 0.0f;
            for (int j = 0; j < 20; j++) at += sA[b * 20 + j];
            at *= (1.0f / (float)SPP);
            float r = fmaxf(at - A_gt[b], 0.0f);
            L_ol += r * r;
        }
        L_ol *= (1.0f / (float)B);
        out[0] = L_chd + L_mc + L_F + L_E + L_G + L_st + L_ol;
        g_done = 0;   // reset for next launch/replay
    }
}

extern "C" void kernel_launch(void* const* d_in, const int* in_sizes, int n_in,
                              void* d_out, int out_size) {
    (void)in_sizes; (void)n_in; (void)out_size;
    const float* pc_gt   = (const float*)d_in[0];
    const float* pc_pred = (const float*)d_in[1];
    const float* fffp    = (const float*)d_in[2];
    const float* A_gt    = (const float*)d_in[3];
    float* out = (float*)d_out;

    k_mega  <<<NBLK_C, 128>>>(pc_pred, pc_gt);
    k_finish<<<FB_T, FT>>>(fffp, A_gt, out);
}

// round 15
// speedup vs baseline: 1.1702x; 1.0329x over previous
#include <cuda_runtime.h>

#define DEV __device__ __forceinline__

constexpr int B    = 8;
constexpr int N    = 8192;
constexpr int M    = 2500;
constexpr int SPP  = 250;    // M / P(=10)

// joint tile: 64 queries x 1024 candidates per block (CPT=8), ILP=2 queries/iter
constexpr int QCH   = 40;              // query chunks (40*64 = 2560 >= 2500)
constexpr int QPB2  = 64;              // queries per block
constexpr int GCH   = 8;               // gt chunks per batch (8*1024 = 8192)
constexpr int CPT   = 8;               // candidates per thread (4 packs)
constexpr int CPW   = 32 * CPT;        // 256 candidates per warp
constexpr int WCH   = N / CPW;         // 32 warp-level candidate chunks
constexpr int NBLK_C = B * QCH * GCH;  // 2560 chamfer blocks

// k_finish decomposition
constexpr int FT    = 128;
constexpr int BM4   = (B * M) / 4;              // 5000 float4 elements (P side)
constexpr int BN4   = (B * N) / 4;              // 16384 float4 elements (G side)
constexpr int FB_F  = 20 * B;                   // 160 fff blocks
constexpr int FB_P  = (BM4 + FT - 1) / FT;      // 40
constexpr int FB_G  = BN4 / FT;                 // 128
constexpr int FB_T  = FB_F + FB_P + FB_G;       // 328

constexpr float BIG = 3.2e38f;

// Partials — every slot written unconditionally; no init kernel, no atomics on data.
__device__ float    g_rowPart[(size_t)WCH * B * M];   // 2.56 MB
__device__ float    g_colPart[(size_t)QCH * B * N];   // 10.5 MB
__device__ float    g_fffp[FB_F * 11];
__device__ float    g_sum2[FB_P + FB_G];
__device__ unsigned g_done;              // zero-init; reset by last block each launch

// ---- packed fp32x2 helpers ----
typedef unsigned long long ull;
DEV ull pack2(float lo, float hi) {
    ull r; asm("mov.b64 %0, {%1, %2};" : "=l"(r) : "f"(lo), "f"(hi)); return r;
}
DEV void unpack2(ull v, float& lo, float& hi) {
    asm("mov.b64 {%0, %1}, %2;" : "=f"(lo), "=f"(hi) : "l"(v));
}
DEV ull fma2(ull a, ull b, ull c) {
    ull d; asm("fma.rn.f32x2 %0, %1, %2, %3;" : "=l"(d) : "l"(a), "l"(b), "l"(c)); return d;
}
DEV ull add2(ull a, ull b) {
    ull d; asm("add.rn.f32x2 %0, %1, %2;" : "=l"(d) : "l"(a), "l"(b)); return d;
}
DEV float4 min4(float4 a, float4 b) {
    return make_float4(fminf(a.x, b.x), fminf(a.y, b.y),
                       fminf(a.z, b.z), fminf(a.w, b.w));
}

DEV float blockReduceSum(float v) {
    __shared__ float sred[32];
    #pragma unroll
    for (int o = 16; o > 0; o >>= 1) v += __shfl_down_sync(0xffffffffu, v, o);
    int lane = threadIdx.x & 31, w = threadIdx.x >> 5;
    if (lane == 0) sred[w] = v;
    __syncthreads();
    int nw = (blockDim.x + 31) >> 5;
    v = (threadIdx.x < (unsigned)nw) ? sred[threadIdx.x] : 0.0f;
    if (w == 0) {
        #pragma unroll
        for (int o = 16; o > 0; o >>= 1) v += __shfl_down_sync(0xffffffffu, v, o);
    }
    __syncthreads();
    return v;
}

// ================= K1: pure chamfer, 2 independent query chains per iter ==========
__global__ void __launch_bounds__(128, 6) k_mega(const float* __restrict__ pred,
                                                 const float* __restrict__ gt) {
    int bid = blockIdx.x;
    int tid = threadIdx.x;

    __shared__ ulonglong2 qs[QPB2][2];          // [0]={qx2,qy2} [1]={qz2,qn2}
    __shared__ float      rowTmp[4][QPB2 * 33]; // [warp][s*33 + lane]

    int gi = bid & (GCH - 1);
    int qi = (bid >> 3) % QCH;
    int b  = bid / (GCH * QCH);
    int w    = tid >> 5;
    int lane = tid & 31;
    int qbase = qi * QPB2;

    if (tid < QPB2) {
        int m = qbase + tid;
        float x = 0.f, y = 0.f, z = 0.f, n = BIG;
        if (m < M) {
            const float* p = pred + (size_t)(b * M + m) * 3;
            x = p[0]; y = p[1]; z = p[2];
            n = x * x + y * y + z * z;
        }
        ulonglong2 u0, u1;
        u0.x = pack2(-2.f * x, -2.f * x);
        u0.y = pack2(-2.f * y, -2.f * y);
        u1.x = pack2(-2.f * z, -2.f * z);
        u1.y = pack2(n, n);
        qs[tid][0] = u0;
        qs[tid][1] = u1;
    }

    int cbase = gi * (4 * CPW) + w * CPW + lane * CPT;
    const float4* gsrc = (const float4*)(gt + (size_t)(b * N + cbase) * 3);
    float4 f0 = gsrc[0], f1 = gsrc[1], f2 = gsrc[2];
    float4 f3 = gsrc[3], f4 = gsrc[4], f5 = gsrc[5];
    float cf[24] = {f0.x,f0.y,f0.z,f0.w, f1.x,f1.y,f1.z,f1.w,
                    f2.x,f2.y,f2.z,f2.w, f3.x,f3.y,f3.z,f3.w,
                    f4.x,f4.y,f4.z,f4.w, f5.x,f5.y,f5.z,f5.w};
    ull cx[4], cy[4], cz[4], gn[4];
    #pragma unroll
    for (int k = 0; k < 4; k++) {
        float x0 = cf[6*k+0], y0 = cf[6*k+1], z0 = cf[6*k+2];
        float x1 = cf[6*k+3], y1 = cf[6*k+4], z1 = cf[6*k+5];
        cx[k] = pack2(x0, x1);
        cy[k] = pack2(y0, y1);
        cz[k] = pack2(z0, z1);
        gn[k] = pack2(x0*x0 + y0*y0 + z0*z0, x1*x1 + y1*y1 + z1*z1);
    }
    float cm[8];
    #pragma unroll
    for (int k = 0; k < 8; k++) cm[k] = BIG;
    __syncthreads();

    #pragma unroll 2
    for (int s = 0; s < QPB2 / 2; s++) {
        ulonglong2 aA = qs[s][0],      cA = qs[s][1];
        ulonglong2 aB = qs[s + 32][0], cB = qs[s + 32][1];

        ull tA0 = fma2(cx[0], aA.x, fma2(cy[0], aA.y, fma2(cz[0], cA.x, cA.y)));
        ull tB0 = fma2(cx[0], aB.x, fma2(cy[0], aB.y, fma2(cz[0], cB.x, cB.y)));
        ull tA1 = fma2(cx[1], aA.x, fma2(cy[1], aA.y, fma2(cz[1], cA.x, cA.y)));
        ull tB1 = fma2(cx[1], aB.x, fma2(cy[1], aB.y, fma2(cz[1], cB.x, cB.y)));
        ull tA2 = fma2(cx[2], aA.x, fma2(cy[2], aA.y, fma2(cz[2], cA.x, cA.y)));
        ull tB2 = fma2(cx[2], aB.x, fma2(cy[2], aB.y, fma2(cz[2], cB.x, cB.y)));
        ull tA3 = fma2(cx[3], aA.x, fma2(cy[3], aA.y, fma2(cz[3], cA.x, cA.y)));
        ull tB3 = fma2(cx[3], aB.x, fma2(cy[3], aB.y, fma2(cz[3], cB.x, cB.y)));

        float l, h;
        unpack2(tA0, l, h); cm[0] = fminf(cm[0], l); cm[1] = fminf(cm[1], h);
        unpack2(tB0, l, h); cm[0] = fminf(cm[0], l); cm[1] = fminf(cm[1], h);
        unpack2(tA1, l, h); cm[2] = fminf(cm[2], l); cm[3] = fminf(cm[3], h);
        unpack2(tB1, l, h); cm[2] = fminf(cm[2], l); cm[3] = fminf(cm[3], h);
        unpack2(tA2, l, h); cm[4] = fminf(cm[4], l); cm[5] = fminf(cm[5], h);
        unpack2(tB2, l, h); cm[4] = fminf(cm[4], l); cm[5] = fminf(cm[5], h);
        unpack2(tA3, l, h); cm[6] = fminf(cm[6], l); cm[7] = fminf(cm[7], h);
        unpack2(tB3, l, h); cm[6] = fminf(cm[6], l); cm[7] = fminf(cm[7], h);

        {
            float r0l, r0h, r1l, r1h, r2l, r2h, r3l, r3h;
            unpack2(add2(tA0, gn[0]), r0l, r0h);
            unpack2(add2(tA1, gn[1]), r1l, r1h);
            unpack2(add2(tA2, gn[2]), r2l, r2h);
            unpack2(add2(tA3, gn[3]), r3l, r3h);
            float rv = fminf(fminf(fminf(r0l, r0h), fminf(r1l, r1h)),
                             fminf(fminf(r2l, r2h), fminf(r3l, r3h)));
            rowTmp[w][s * 33 + lane] = rv;
        }
        {
            float r0l, r0h, r1l, r1h, r2l, r2h, r3l, r3h;
            unpack2(add2(tB0, gn[0]), r0l, r0h);
            unpack2(add2(tB1, gn[1]), r1l, r1h);
            unpack2(add2(tB2, gn[2]), r2l, r2h);
            unpack2(add2(tB3, gn[3]), r3l, r3h);
            float rv = fminf(fminf(fminf(r0l, r0h), fminf(r1l, r1h)),
                             fminf(fminf(r2l, r2h), fminf(r3l, r3h)));
            rowTmp[w][(s + 32) * 33 + lane] = rv;
        }
    }

    {
        float n0, n1, n2, n3, n4, n5, n6, n7;
        unpack2(gn[0], n0, n1); unpack2(gn[1], n2, n3);
        unpack2(gn[2], n4, n5); unpack2(gn[3], n6, n7);
        float4* outc = (float4*)(g_colPart + (size_t)qi * (B * N) + b * N + cbase);
        outc[0] = make_float4(fmaxf(cm[0] + n0, 0.f), fmaxf(cm[1] + n1, 0.f),
                              fmaxf(cm[2] + n2, 0.f), fmaxf(cm[3] + n3, 0.f));
        outc[1] = make_float4(fmaxf(cm[4] + n4, 0.f), fmaxf(cm[5] + n5, 0.f),
                              fmaxf(cm[6] + n6, 0.f), fmaxf(cm[7] + n7, 0.f));
    }
    __syncthreads();

    for (int idx = tid; idx < 4 * QPB2; idx += 128) {
        int ww = idx >> 6;
        int s  = idx & (QPB2 - 1);
        const float* src = &rowTmp[ww][s * 33];
        float f = src[0];
        #pragma unroll
        for (int l2 = 1; l2 < 32; l2++) f = fminf(f, src[l2]);
        int m = qbase + s;
        if (m < M) {
            int ch = gi * 4 + ww;
            g_rowPart[(size_t)ch * (B * M) + b * M + m] = f;
        }
    }
}

// ====== K2: finish — high-MLP chunk mins; LAST block does final combine =====
__global__ void __launch_bounds__(FT) k_finish(const float* __restrict__ fff,
                                               const float* __restrict__ A_gt,
                                               float* __restrict__ out) {
    int bid = blockIdx.x;
    int tid = threadIdx.x;
    __shared__ unsigned sLast;

    if (bid < FB_F) {
        int b = bid / 20;
        int m = (bid % 20) * FT + tid;
        float v[11];
        #pragma unroll
        for (int i = 0; i < 11; i++) v[i] = 0.0f;
        if (m < M) {
            int idx = (b * M + m) * 3;
            float E = fff[idx], F = fff[idx + 1], G = fff[idx + 2];
            float A2  = fmaxf(E * G - F * F, 0.0f);
            float A   = sqrtf(A2);
            float inv = 1.0f / (A2 + 1e-20f);
            v[0] = E;        v[1] = G;        v[2] = inv;
            v[3] = E * inv;  v[4] = E * E * inv;
            v[5] = G * inv;  v[6] = G * G * inv;
            v[7] = F * F * inv;
            float d = E - G; v[8] = d * d * inv;
            if ((b & 1) == 0) {
                int idx2 = ((b + 1) * M + m) * 3;
                float E2 = fff[idx2], F2 = fff[idx2 + 1], G2 = fff[idx2 + 2];
                float dE = E - E2, dF = F - F2, dG = G - G2;
                v[9] = dE * dE + 2.0f * dF * dF + dG * dG;
            }
            v[10] = A;
        }
        #pragma unroll
        for (int k = 0; k < 11; k++) {
            float s = blockReduceSum(v[k]);
            if (tid == 0) g_fffp[bid * 11 + k] = s;
        }
    } else {
        int fb = bid - FB_F;
        float d = 0.0f;
        if (fb < FB_P) {
            // P side: rowPart, WCH=32 chunks, float4 over 4 queries, 8-way MLP
            int e = fb * FT + tid;          // [0, BM4)
            if (e < BM4) {
                const float4* rp = (const float4*)g_rowPart;
                float4 acc[8];
                #pragma unroll
                for (int j = 0; j < 8; j++)
                    acc[j] = rp[(size_t)j * BM4 + e];
                #pragma unroll
                for (int t = 1; t < 4; t++) {
                    float4 v[8];
                    #pragma unroll
                    for (int j = 0; j < 8; j++)
                        v[j] = rp[(size_t)(t * 8 + j) * BM4 + e];
                    #pragma unroll
                    for (int j = 0; j < 8; j++)
                        acc[j] = min4(acc[j], v[j]);
                }
                float4 f = min4(min4(acc[0], acc[1]), min4(acc[2], acc[3]));
                f = min4(f, min4(min4(acc[4], acc[5]), min4(acc[6], acc[7])));
                d = fmaxf(f.x, 0.f) + fmaxf(f.y, 0.f) + fmaxf(f.z, 0.f) + fmaxf(f.w, 0.f);
            }
        } else {
            // G side: colPart, QCH=40 chunks, float4, 8-way MLP
            int e = (fb - FB_P) * FT + tid;  // [0, BN4), exact
            const float4* cp = (const float4*)g_colPart;
            float4 acc[8];
            #pragma unroll
            for (int j = 0; j < 8; j++)
                acc[j] = cp[(size_t)j * BN4 + e];
            #pragma unroll
            for (int t = 1; t < 5; t++) {
                float4 v[8];
                #pragma unroll
                for (int j = 0; j < 8; j++)
                    v[j] = cp[(size_t)(t * 8 + j) * BN4 + e];
                #pragma unroll
                for (int j = 0; j < 8; j++)
                    acc[j] = min4(acc[j], v[j]);
            }
            float4 f = min4(min4(acc[0], acc[1]), min4(acc[2], acc[3]));
            f = min4(f, min4(min4(acc[4], acc[5]), min4(acc[6], acc[7])));
            d = f.x + f.y + f.z + f.w;      // already clamped at write
        }
        float s = blockReduceSum(d);
        if (tid == 0) g_sum2[fb] = s;
    }

    // last-block-does-final
    __threadfence();
    if (tid == 0) sLast = (atomicAdd(&g_done, 1u) == (unsigned)(FB_T - 1));
    __syncthreads();
    if (!sLast) return;
    __threadfence();   // acquire

    __shared__ float sA[FB_F];
    __shared__ float acc2[12];
    #pragma unroll
    for (int k = 0; k < 10; k++) {
        float v = 0.0f;
        for (int j = tid; j < FB_F; j += FT) v += g_fffp[j * 11 + k];
        float s = blockReduceSum(v);
        if (tid == 0) acc2[k] = s;
    }
    {
        float v = 0.0f;
        for (int j = tid; j < FB_P; j += FT) v += g_sum2[j];
        float s = blockReduceSum(v);
        if (tid == 0) acc2[10] = s;
        v = 0.0f;
        for (int j = tid; j < FB_G; j += FT) v += g_sum2[FB_P + j];
        s = blockReduceSum(v);
        if (tid == 0) acc2[11] = s;
    }
    for (int j = tid; j < FB_F; j += FT) sA[j] = g_fffp[j * 11 + 10];
    __syncthreads();

    if (tid == 0) {
        float BM = (float)(B * M);
        float L_chd = acc2[10] / BM + acc2[11] / (float)(B * N);
        float sE = acc2[0], sG = acc2[1], sInv = acc2[2];
        float sEinv = acc2[3], sE2inv = acc2[4], sGinv = acc2[5], sG2inv = acc2[6];
        float sF2inv = acc2[7], sStretch = acc2[8], sMc = acc2[9];
        float mE = sE / BM, mG = sG / BM;
        float L_E  = (sE2inv - 2.0f * mE * sEinv + mE * mE * sInv) / BM;
        float L_G  = (sG2inv - 2.0f * mG * sGinv + mG * mG * sInv) / BM;
        float L_F  = sF2inv  / BM;
        float L_st = sStretch / BM;
        float L_mc = sMc / (0.5f * BM);
        float L_ol = 0.0f;
        for (int b = 0; b < B; b++) {
            float at = 0.0f;
            for (int j = 0; j < 20; j++) at += sA[b * 20 + j];
            at *= (1.0f / (float)SPP);
            float r = fmaxf(at - A_gt[b], 0.0f);
            L_ol += r * r;
        }
        L_ol *= (1.0f / (float)B);
        out[0] = L_chd + L_mc + L_F + L_E + L_G + L_st + L_ol;
        g_done = 0;   // reset for next launch/replay
    }
}

extern "C" void kernel_launch(void* const* d_in, const int* in_sizes, int n_in,
                              void* d_out, int out_size) {
    (void)in_sizes; (void)n_in; (void)out_size;
    const float* pc_gt   = (const float*)d_in[0];
    const float* pc_pred = (const float*)d_in[1];
    const float* fffp    = (const float*)d_in[2];
    const float* A_gt    = (const float*)d_in[3];
    float* out = (float*)d_out;

    k_mega  <<<NBLK_C, 128>>>(pc_pred, pc_gt);
    k_finish<<<FB_T, FT>>>(fffp, A_gt, out);
}